// round 15
// baseline (speedup 1.0000x reference)
#include <cuda_runtime.h>
#include <cuda_fp16.h>
#include <math.h>
#include <stdint.h>

#define BB 4
#define NN 1024
#define DD 1024
#define HH 16
#define HD 64
#define BH (BB*HH)

// ---------------- scratch (device globals; allocation-free) ----------------
__device__ __half g_xh[BB*NN*DD];      // x hi
__device__ __half g_xl[BB*NN*DD];      // x lo
__device__ __half g_w[4][DD*DD];       // Wq,Wk,Wv,Wo fp16

__device__ __half g_qh[BH*NN*HD];      // Q hi (pre-scaled by 0.125)
__device__ __half g_ql[BH*NN*HD];      // Q lo
__device__ __half g_k [BH*NN*HD];      // K single
__device__ __half g_v [BH*NN*HD];      // V single

__device__ __half g_oh[BB*NN*DD];      // attention out hi [B,N,D]
__device__ __half g_ol[BB*NN*DD];      // attention out lo

// ---------------- helpers ----------------
__device__ __forceinline__ uint32_t smem_u32(const void* p) {
    uint32_t a;
    asm("{ .reg .u64 t; cvta.to.shared.u64 t, %1; cvt.u32.u64 %0, t; }" : "=r"(a) : "l"(p));
    return a;
}
__device__ __forceinline__ void mma16816(float* d, const uint32_t* a, const uint32_t* b) {
    asm volatile(
        "mma.sync.aligned.m16n8k16.row.col.f32.f16.f16.f32 "
        "{%0,%1,%2,%3}, {%4,%5,%6,%7}, {%8,%9}, {%0,%1,%2,%3};"
        : "+f"(d[0]), "+f"(d[1]), "+f"(d[2]), "+f"(d[3])
        : "r"(a[0]), "r"(a[1]), "r"(a[2]), "r"(a[3]), "r"(b[0]), "r"(b[1]));
}
__device__ __forceinline__ void ldsm_x4(uint32_t* r, uint32_t addr) {
    asm volatile("ldmatrix.sync.aligned.m8n8.x4.shared.b16 {%0,%1,%2,%3}, [%4];"
        : "=r"(r[0]), "=r"(r[1]), "=r"(r[2]), "=r"(r[3]) : "r"(addr));
}
__device__ __forceinline__ void ldsm_x4_t(uint32_t* r, uint32_t addr) {
    asm volatile("ldmatrix.sync.aligned.m8n8.x4.trans.shared.b16 {%0,%1,%2,%3}, [%4];"
        : "=r"(r[0]), "=r"(r[1]), "=r"(r[2]), "=r"(r[3]) : "r"(addr));
}
#define CP_ASYNC16(sdst, gsrc) \
    asm volatile("cp.async.cg.shared.global [%0], [%1], 16;" :: "r"(sdst), "l"(gsrc))
#define CP_COMMIT() asm volatile("cp.async.commit_group;" ::: "memory")
#define CP_WAIT0()  asm volatile("cp.async.wait_group 0;" ::: "memory")
#define CP_WAIT1()  asm volatile("cp.async.wait_group 1;" ::: "memory")

#define SWZ(o) ((o) ^ (((o) >> 3) & 0x70))    // SW128 for 128-byte rows

__device__ __forceinline__ void packsplit_h(float f0, float f1, uint32_t& hi, uint32_t& lo) {
    __half2 h = __floats2half2_rn(f0, f1);
    float r0 = f0 - __low2float(h);
    float r1 = f1 - __high2float(h);
    __half2 l = __floats2half2_rn(r0, r1);
    hi = *reinterpret_cast<uint32_t*>(&h);
    lo = *reinterpret_cast<uint32_t*>(&l);
}
__device__ __forceinline__ uint32_t pack_h(float f0, float f1) {
    __half2 h = __floats2half2_rn(f0, f1);
    return *reinterpret_cast<uint32_t*>(&h);
}

// ---------------- prep kernels ----------------
__global__ __launch_bounds__(256) void split_x_kernel(const float* __restrict__ s,
                                                      __half* __restrict__ h,
                                                      __half* __restrict__ l, int n2)
{
    int i = blockIdx.x * 256 + threadIdx.x;
    if (i < n2) {
        float2 v = ((const float2*)s)[i];
        uint32_t hi, lo;
        packsplit_h(v.x, v.y, hi, lo);
        ((uint32_t*)h)[i] = hi;
        ((uint32_t*)l)[i] = lo;
    }
}
__global__ __launch_bounds__(256) void round_w4_kernel(
    const float* __restrict__ w0, const float* __restrict__ w1,
    const float* __restrict__ w2, const float* __restrict__ w3,
    __half* __restrict__ h, int n2)
{
    const float* src[4] = {w0, w1, w2, w3};
    int i = blockIdx.x * 256 + threadIdx.x;
    if (i < n2) {
        float2 v = ((const float2*)src[blockIdx.y])[i];
        ((uint32_t*)h)[(size_t)blockIdx.y * n2 + i] = pack_h(v.x, v.y);
    }
}

// ---------------- 2-term fp16 GEMM (HMMA + ldmatrix, 3-stage cp.async) ----------------
#define KS 32
#define SS 40
#define RB (SS*2)
#define TILE_BYTES (128*RB)
#define STAGE_BYTES (3*TILE_BYTES)
#define GSMEM_BYTES (3*STAGE_BYTES)
#define NSTG (DD/KS)

template<int MODE>
__global__ __launch_bounds__(256, 2) void gemm_mma(
    const __half* __restrict__ Ah, const __half* __restrict__ Al,
    const __half* __restrict__ Bw,
    float* __restrict__ outF, __half* __restrict__ o1,
    __half* __restrict__ o2, __half* __restrict__ o3)
{
    extern __shared__ __align__(16) char smem[];
    const int tid = threadIdx.x;
    const int wid = tid >> 5, lane = tid & 31;
    const int g = lane >> 2, tg = lane & 3;
    const int m0 = blockIdx.y * 128, n0 = blockIdx.x * 128;
    const int wm = (wid & 1) * 64, wn = (wid >> 1) * 32;
    const int z = (MODE == 1) ? blockIdx.z : 0;

    const uint32_t sbase = smem_u32(smem);
    const __half* Bz = (MODE == 1) ? (Bw + (size_t)z * DD * DD) : Bw;
    const __half* srcs[3] = {Ah, Al, Bz};

    auto prefetch = [&](int s) {
        const int k0 = s * KS;
        const uint32_t dst0 = sbase + (uint32_t)(s % 3) * STAGE_BYTES;
#pragma unroll
        for (int t = 0; t < 3; t++) {
            const __half* sp = srcs[t];
            const int rb = (t < 2) ? m0 : n0;
#pragma unroll
            for (int i = 0; i < 2; i++) {
                int idx = tid + i * 256;
                int row = idx >> 2, c = idx & 3;
                const void* gsrc = sp + (size_t)(rb + row) * DD + k0 + c * 8;
                CP_ASYNC16(dst0 + t * TILE_BYTES + row * RB + c * 16, gsrc);
            }
        }
        CP_COMMIT();
    };

    float acc[4][4][4];
#pragma unroll
    for (int i = 0; i < 4; i++)
#pragma unroll
        for (int j = 0; j < 4; j++)
#pragma unroll
            for (int c = 0; c < 4; c++) acc[i][j][c] = 0.f;

    const uint32_t laneA = (lane & 15) * RB + (lane >> 4) * 16;
    const uint32_t laneB = ((lane & 7) + (lane >> 4) * 8) * RB + ((lane >> 3) & 1) * 16;

    prefetch(0);
    prefetch(1);
    for (int s = 0; s < NSTG; s++) {
        if (s == NSTG - 1) { CP_WAIT0(); } else { CP_WAIT1(); }
        __syncthreads();
        if (s + 2 < NSTG) prefetch(s + 2);
        const uint32_t st = sbase + (uint32_t)(s % 3) * STAGE_BYTES;

#pragma unroll
        for (int ks = 0; ks < 2; ks++) {
            const int kb2 = ks * 32;
            uint32_t ah[4][4], al[4][4], bh[8];
#pragma unroll
            for (int i = 0; i < 4; i++) {
                uint32_t aA = st + (wm + 16 * i) * RB + kb2 + laneA;
                ldsm_x4(ah[i], aA);
                ldsm_x4(al[i], aA + TILE_BYTES);
            }
            {
                uint32_t b0 = st + 2 * TILE_BYTES + wn * RB + kb2 + laneB;
                ldsm_x4(bh,     b0);
                ldsm_x4(bh + 4, b0 + 16 * RB);
            }
#pragma unroll
            for (int i = 0; i < 4; i++)
#pragma unroll
                for (int j = 0; j < 4; j++) {
                    mma16816(acc[i][j], ah[i], bh + 2 * j);
                    mma16816(acc[i][j], al[i], bh + 2 * j);
                }
        }
    }

#pragma unroll
    for (int i = 0; i < 4; i++) {
        int mA = m0 + wm + i * 16 + g;
#pragma unroll
        for (int j = 0; j < 4; j++) {
            int c = n0 + wn + j * 8 + 2 * tg;
            if (MODE == 0) {
                *(float2*)(outF + (size_t)mA * DD + c) =
                    make_float2(acc[i][j][0], acc[i][j][1]);
                *(float2*)(outF + (size_t)(mA + 8) * DD + c) =
                    make_float2(acc[i][j][2], acc[i][j][3]);
            } else {
                int h = c >> 6, t = c & 63;
                int b1 = mA >> 10, n1 = mA & 1023;
                int b2 = (mA + 8) >> 10, n2 = (mA + 8) & 1023;
                size_t i1 = ((size_t)(b1 * HH + h) * NN + n1) * HD + t;
                size_t i2 = ((size_t)(b2 * HH + h) * NN + n2) * HD + t;
                if (z == 0) {
                    uint32_t hi, lo;
                    packsplit_h(acc[i][j][0] * 0.125f, acc[i][j][1] * 0.125f, hi, lo);
                    *(uint32_t*)(o1 + i1) = hi;
                    *(uint32_t*)(o2 + i1) = lo;
                    packsplit_h(acc[i][j][2] * 0.125f, acc[i][j][3] * 0.125f, hi, lo);
                    *(uint32_t*)(o1 + i2) = hi;
                    *(uint32_t*)(o2 + i2) = lo;
                } else {
                    __half* dst = (z == 1) ? o3 : (o3 + (size_t)BH * NN * HD);
                    *(uint32_t*)(dst + i1) = pack_h(acc[i][j][0], acc[i][j][1]);
                    *(uint32_t*)(dst + i2) = pack_h(acc[i][j][2], acc[i][j][3]);
                }
            }
        }
    }
}

// ---------------- flash attention (fp16 2-term, cp.async bias, key-split warps) ----------------
// 512 threads, 1 CTA/SM. Warps 0-7: keys 0-63 of each chunk; warps 8-15: keys 64-127.
// smem: [K0 16K][V0 16K][K1 16K][V1 16K][bias0 68K][bias1 68K]; Q aliased into bias1 at c=0.
#define KTILE 16384
#define KV_STAGE (2*KTILE)             // 32768 per stage
#define BIAS0_OFF 65536
#define BIAS_ROWB 544                  // 136 floats/row (conflict-free half-warp LDS.64)
#define BIAS_STAGE (128*BIAS_ROWB)     // 69632
#define QALIAS_OFF (BIAS0_OFF + BIAS_STAGE)
#define ASMEM (BIAS0_OFF + 2*BIAS_STAGE)   // 204800
#define SOFF 8.0f

__global__ __launch_bounds__(512, 1) void attn_mma(const float* __restrict__ bias)
{
    extern __shared__ __align__(1024) char smem[];
    const int tid = threadIdx.x, wid = tid >> 5, lane = tid & 31;
    const int g = lane >> 2, tg = lane & 3;
    const int half = wid >> 3;             // 0: keys 0-63, 1: keys 64-127
    const int wq = (wid & 7) * 16;         // q-row tile of this warp
    const int bh = blockIdx.x;
    const int row0 = blockIdx.y * 128;
    const uint32_t sb = smem_u32(smem);

    const __half* qhp = g_qh + (size_t)bh * NN * HD;
    const __half* qlp = g_ql + (size_t)bh * NN * HD;
    const __half* kp  = g_k  + (size_t)bh * NN * HD;
    const __half* vp  = g_v  + (size_t)bh * NN * HD;
    const float*  bsrc = bias + ((size_t)bh * NN + row0) * NN;

    // issue K(c), V(c), bias(c) as ONE commit group
    auto issue_kvb = [&](int c) {
        const uint32_t kvst = sb + (uint32_t)(c & 1) * KV_STAGE;
#pragma unroll
        for (int i = 0; i < 2; i++) {
            int idx = tid + i * 512;               // 0..1023
            int row = idx >> 3, ch = idx & 7;
            size_t go = (size_t)(c * 128 + row) * HD + ch * 8;
            uint32_t so = SWZ((uint32_t)(row * 128 + ch * 16));
            CP_ASYNC16(kvst + so,         kp + go);
            CP_ASYNC16(kvst + KTILE + so, vp + go);
        }
        const uint32_t bst = sb + BIAS0_OFF + (uint32_t)(c & 1) * BIAS_STAGE;
#pragma unroll
        for (int i = 0; i < 8; i++) {
            int idx = tid + i * 512;               // 0..4095
            int row = idx >> 5, c16 = idx & 31;
            CP_ASYNC16(bst + (uint32_t)row * BIAS_ROWB + c16 * 16,
                       bsrc + (size_t)row * NN + c * 128 + c16 * 4);
        }
        CP_COMMIT();
    };

    // prologue: Q (into bias1 alias region) + chunk0 K/V/bias, one group
#pragma unroll
    for (int i = 0; i < 2; i++) {
        int idx = tid + i * 512;
        int row = idx >> 3, ch = idx & 7;
        size_t go = (size_t)(row0 + row) * HD + ch * 8;
        uint32_t so = SWZ((uint32_t)(row * 128 + ch * 16));
        CP_ASYNC16(sb + QALIAS_OFF + so,         qhp + go);
        CP_ASYNC16(sb + QALIAS_OFF + KTILE + so, qlp + go);
    }
    {
        const uint32_t kvst = sb;
#pragma unroll
        for (int i = 0; i < 2; i++) {
            int idx = tid + i * 512;
            int row = idx >> 3, ch = idx & 7;
            size_t go = (size_t)(row) * HD + ch * 8;
            uint32_t so = SWZ((uint32_t)(row * 128 + ch * 16));
            CP_ASYNC16(kvst + so,         kp + go);
            CP_ASYNC16(kvst + KTILE + so, vp + go);
        }
        const uint32_t bst = sb + BIAS0_OFF;
#pragma unroll
        for (int i = 0; i < 8; i++) {
            int idx = tid + i * 512;
            int row = idx >> 5, c16 = idx & 31;
            CP_ASYNC16(bst + (uint32_t)row * BIAS_ROWB + c16 * 16,
                       bsrc + (size_t)row * NN + c16 * 4);
        }
        CP_COMMIT();
    }

    float sA[8][4];
    float O[8][4];
#pragma unroll
    for (int j = 0; j < 8; j++)
#pragma unroll
        for (int c = 0; c < 4; c++) O[j][c] = 0.f;
    float ls[2] = {0.f, 0.f};
    uint32_t qfh[4][4], qfl[4][4];

    for (int c = 0; c < 8; c++) {
        CP_WAIT0();
        __syncthreads();
        if (c == 0) {
#pragma unroll
            for (int t = 0; t < 4; t++) {
                uint32_t qoff = (uint32_t)((wq + (lane & 15)) * 128 + t * 32 + (lane >> 4) * 16);
                uint32_t qa = sb + QALIAS_OFF + SWZ(qoff);
                ldsm_x4(qfh[t], qa);
                ldsm_x4(qfl[t], qa + KTILE);
            }
            __syncthreads();   // all Q frags read before bias1 overwrites the alias region
        }
        if (c + 1 < 8) issue_kvb(c + 1);

        // ---- init S from bias (smem) ----
        {
            const float* bsm = (const float*)(smem + BIAS0_OFF + (c & 1) * BIAS_STAGE);
            const float* p0 = bsm + (wq + g) * 136 + half * 64 + 2 * tg;
#pragma unroll
            for (int j = 0; j < 8; j++) {
                float2 u = *(const float2*)(p0 + 8 * j);
                float2 w = *(const float2*)(p0 + 8 * 136 + 8 * j);
                sA[j][0] = u.x; sA[j][1] = u.y; sA[j][2] = w.x; sA[j][3] = w.y;
            }
        }

        const uint32_t kh_b = sb + (uint32_t)(c & 1) * KV_STAGE;

        // ---- S += Q K^T (this warp's 64 keys) ----
#pragma unroll 4
        for (int j = 0; j < 8; j++) {
            uint32_t kf[8];
            uint32_t koff = (uint32_t)((half * 64 + j * 8 + (lane & 7)) * 128 + (lane >> 3) * 16);
            ldsm_x4(kf,     kh_b + SWZ(koff));
            ldsm_x4(kf + 4, kh_b + SWZ(koff + 64));
#pragma unroll
            for (int t = 0; t < 4; t++) {
                mma16816(sA[j], qfh[t], kf + 2 * t);
                mma16816(sA[j], qfl[t], kf + 2 * t);
            }
        }

        // ---- P = exp(S - SOFF); partial row sums ----
        {
            float p0 = 0.f, p1 = 0.f;
#pragma unroll
            for (int j = 0; j < 8; j++) {
                float e0 = __expf(sA[j][0] - SOFF);
                float e1 = __expf(sA[j][1] - SOFF);
                float e2 = __expf(sA[j][2] - SOFF);
                float e3 = __expf(sA[j][3] - SOFF);
                sA[j][0] = e0; sA[j][1] = e1; sA[j][2] = e2; sA[j][3] = e3;
                p0 += e0 + e1;
                p1 += e2 + e3;
            }
            ls[0] += p0;
            ls[1] += p1;
        }

        // ---- O += P V (this warp's 64 keys; P split hi/lo, V single) ----
        const uint32_t vh_b = kh_b + KTILE;
#pragma unroll 2
        for (int t = 0; t < 4; t++) {
            uint32_t aph[4], apl[4];
            packsplit_h(sA[2 * t][0],     sA[2 * t][1],     aph[0], apl[0]);
            packsplit_h(sA[2 * t][2],     sA[2 * t][3],     aph[1], apl[1]);
            packsplit_h(sA[2 * t + 1][0], sA[2 * t + 1][1], aph[2], apl[2]);
            packsplit_h(sA[2 * t + 1][2], sA[2 * t + 1][3], aph[3], apl[3]);
#pragma unroll
            for (int jp = 0; jp < 8; jp += 2) {
                uint32_t vf[4];
                uint32_t voff = (uint32_t)((half * 64 + t * 16 + (lane & 7) + ((lane >> 3) & 1) * 8) * 128
                                           + jp * 16 + (lane >> 4) * 16);
                ldsm_x4_t(vf, vh_b + SWZ(voff));
                mma16816(O[jp],     aph, vf);
                mma16816(O[jp],     apl, vf);
                mma16816(O[jp + 1], aph, vf + 2);
                mma16816(O[jp + 1], apl, vf + 2);
            }
        }
    }

    // ---- merge the two key-halves (partner warps wid <-> wid+8) via smem ----
    __syncthreads();   // all PV done; KV smem free for exchange
    float* exch = (float*)smem;
    if (half == 1) {
        float* ex = exch + (((wid - 8) * 32 + lane) * 34);
#pragma unroll
        for (int jo = 0; jo < 8; jo++) {
            ex[jo * 4 + 0] = O[jo][0]; ex[jo * 4 + 1] = O[jo][1];
            ex[jo * 4 + 2] = O[jo][2]; ex[jo * 4 + 3] = O[jo][3];
        }
        ex[32] = ls[0];
        ex[33] = ls[1];
    }
    __syncthreads();
    if (half == 0) {
        const float* ex = exch + ((wid * 32 + lane) * 34);
#pragma unroll
        for (int jo = 0; jo < 8; jo++) {
            O[jo][0] += ex[jo * 4 + 0]; O[jo][1] += ex[jo * 4 + 1];
            O[jo][2] += ex[jo * 4 + 2]; O[jo][3] += ex[jo * 4 + 3];
        }
        ls[0] += ex[32];
        ls[1] += ex[33];

        float inv[2];
#pragma unroll
        for (int h = 0; h < 2; h++) {
            float v = ls[h];
            v += __shfl_xor_sync(0xffffffffu, v, 1);
            v += __shfl_xor_sync(0xffffffffu, v, 2);
            inv[h] = 1.0f / v;
        }
        const int b = bh >> 4, hh = bh & 15;
        const size_t r1 = ((size_t)(b * NN + row0 + wq + g)) * DD + hh * HD + 2 * tg;
        const size_t r2 = r1 + (size_t)8 * DD;
#pragma unroll
        for (int jo = 0; jo < 8; jo++) {
            uint32_t hi, lo;
            packsplit_h(O[jo][0] * inv[0], O[jo][1] * inv[0], hi, lo);
            *(uint32_t*)(g_oh + r1 + 8 * jo) = hi;
            *(uint32_t*)(g_ol + r1 + 8 * jo) = lo;
            packsplit_h(O[jo][2] * inv[1], O[jo][3] * inv[1], hi, lo);
            *(uint32_t*)(g_oh + r2 + 8 * jo) = hi;
            *(uint32_t*)(g_ol + r2 + 8 * jo) = lo;
        }
    }
}

// ---------------- launch ----------------
extern "C" void kernel_launch(void* const* d_in, const int* in_sizes, int n_in,
                              void* d_out, int out_size)
{
    const float* x    = (const float*)d_in[0];
    const float* bias = (const float*)d_in[1];
    float* out = (float*)d_out;

    __half *xh, *xl, *wq, *qh, *ql, *kk, *oh, *ol;
    cudaGetSymbolAddress((void**)&xh, g_xh);
    cudaGetSymbolAddress((void**)&xl, g_xl);
    cudaGetSymbolAddress((void**)&wq, g_w);
    cudaGetSymbolAddress((void**)&qh, g_qh);
    cudaGetSymbolAddress((void**)&ql, g_ql);
    cudaGetSymbolAddress((void**)&kk, g_k);
    cudaGetSymbolAddress((void**)&oh, g_oh);
    cudaGetSymbolAddress((void**)&ol, g_ol);

    cudaFuncSetAttribute(gemm_mma<0>, cudaFuncAttributeMaxDynamicSharedMemorySize, GSMEM_BYTES);
    cudaFuncSetAttribute(gemm_mma<1>, cudaFuncAttributeMaxDynamicSharedMemorySize, GSMEM_BYTES);
    cudaFuncSetAttribute(attn_mma, cudaFuncAttributeMaxDynamicSharedMemorySize, ASMEM);

    const int NX = BB*NN*DD;
    const int NW = DD*DD;

    split_x_kernel<<<NX/512, 256>>>(x, xh, xl, NX/2);
    round_w4_kernel<<<dim3(NW/512, 4), 256>>>((const float*)d_in[2], (const float*)d_in[3],
                                              (const float*)d_in[4], (const float*)d_in[5],
                                              wq, NW/2);

    dim3 gqkv(DD/128, (BB*NN)/128, 3);
    gemm_mma<1><<<gqkv, 256, GSMEM_BYTES>>>(xh, xl, wq, nullptr, qh, ql, kk);

    attn_mma<<<dim3(BH, NN/128), 512, ASMEM>>>(bias);

    gemm_mma<0><<<dim3(DD/128, (BB*NN)/128), 256, GSMEM_BYTES>>>(
        oh, ol, wq + 3*(size_t)NW, out, nullptr, nullptr, nullptr);
}

// round 16
// speedup vs baseline: 1.5918x; 1.5918x over previous
#include <cuda_runtime.h>
#include <cuda_fp16.h>
#include <math.h>
#include <stdint.h>

#define BB 4
#define NN 1024
#define DD 1024
#define HH 16
#define HD 64
#define BH (BB*HH)

// ---------------- scratch (device globals; allocation-free) ----------------
__device__ __half g_xh[BB*NN*DD];      // x hi
__device__ __half g_xl[BB*NN*DD];      // x lo
__device__ __half g_w[4][DD*DD];       // Wq,Wk,Wv,Wo fp16

__device__ __half g_qh[BH*NN*HD];      // Q hi (pre-scaled by 0.125)
__device__ __half g_ql[BH*NN*HD];      // Q lo
__device__ __half g_k [BH*NN*HD];      // K single
__device__ __half g_v [BH*NN*HD];      // V single

__device__ __half g_oh[BB*NN*DD];      // attention out hi [B,N,D]
__device__ __half g_ol[BB*NN*DD];      // attention out lo

// ---------------- helpers ----------------
__device__ __forceinline__ uint32_t smem_u32(const void* p) {
    uint32_t a;
    asm("{ .reg .u64 t; cvta.to.shared.u64 t, %1; cvt.u32.u64 %0, t; }" : "=r"(a) : "l"(p));
    return a;
}
__device__ __forceinline__ void mma16816(float* d, const uint32_t* a, const uint32_t* b) {
    asm volatile(
        "mma.sync.aligned.m16n8k16.row.col.f32.f16.f16.f32 "
        "{%0,%1,%2,%3}, {%4,%5,%6,%7}, {%8,%9}, {%0,%1,%2,%3};"
        : "+f"(d[0]), "+f"(d[1]), "+f"(d[2]), "+f"(d[3])
        : "r"(a[0]), "r"(a[1]), "r"(a[2]), "r"(a[3]), "r"(b[0]), "r"(b[1]));
}
__device__ __forceinline__ void ldsm_x4(uint32_t* r, uint32_t addr) {
    asm volatile("ldmatrix.sync.aligned.m8n8.x4.shared.b16 {%0,%1,%2,%3}, [%4];"
        : "=r"(r[0]), "=r"(r[1]), "=r"(r[2]), "=r"(r[3]) : "r"(addr));
}
__device__ __forceinline__ void ldsm_x4_t(uint32_t* r, uint32_t addr) {
    asm volatile("ldmatrix.sync.aligned.m8n8.x4.trans.shared.b16 {%0,%1,%2,%3}, [%4];"
        : "=r"(r[0]), "=r"(r[1]), "=r"(r[2]), "=r"(r[3]) : "r"(addr));
}
#define CP_ASYNC16(sdst, gsrc) \
    asm volatile("cp.async.cg.shared.global [%0], [%1], 16;" :: "r"(sdst), "l"(gsrc))
#define CP_COMMIT() asm volatile("cp.async.commit_group;" ::: "memory")
#define CP_WAIT0()  asm volatile("cp.async.wait_group 0;" ::: "memory")
#define CP_WAIT1()  asm volatile("cp.async.wait_group 1;" ::: "memory")

#define SWZ(o) ((o) ^ (((o) >> 3) & 0x70))    // SW128 for 128-byte rows

__device__ __forceinline__ void packsplit_h(float f0, float f1, uint32_t& hi, uint32_t& lo) {
    __half2 h = __floats2half2_rn(f0, f1);
    float r0 = f0 - __low2float(h);
    float r1 = f1 - __high2float(h);
    __half2 l = __floats2half2_rn(r0, r1);
    hi = *reinterpret_cast<uint32_t*>(&h);
    lo = *reinterpret_cast<uint32_t*>(&l);
}
__device__ __forceinline__ uint32_t pack_h(float f0, float f1) {
    __half2 h = __floats2half2_rn(f0, f1);
    return *reinterpret_cast<uint32_t*>(&h);
}

// ---------------- prep kernels ----------------
__global__ __launch_bounds__(256) void split_x_kernel(const float* __restrict__ s,
                                                      __half* __restrict__ h,
                                                      __half* __restrict__ l, int n2)
{
    int i = blockIdx.x * 256 + threadIdx.x;
    if (i < n2) {
        float2 v = ((const float2*)s)[i];
        uint32_t hi, lo;
        packsplit_h(v.x, v.y, hi, lo);
        ((uint32_t*)h)[i] = hi;
        ((uint32_t*)l)[i] = lo;
    }
}
__global__ __launch_bounds__(256) void round_w4_kernel(
    const float* __restrict__ w0, const float* __restrict__ w1,
    const float* __restrict__ w2, const float* __restrict__ w3,
    __half* __restrict__ h, int n2)
{
    const float* src[4] = {w0, w1, w2, w3};
    int i = blockIdx.x * 256 + threadIdx.x;
    if (i < n2) {
        float2 v = ((const float2*)src[blockIdx.y])[i];
        ((uint32_t*)h)[(size_t)blockIdx.y * n2 + i] = pack_h(v.x, v.y);
    }
}

// ---------------- 2-term fp16 GEMM (HMMA + ldmatrix, 3-stage cp.async) ----------------
#define KS 32
#define SS 40
#define RB (SS*2)
#define TILE_BYTES (128*RB)
#define STAGE_BYTES (3*TILE_BYTES)
#define GSMEM_BYTES (3*STAGE_BYTES)
#define NSTG (DD/KS)

template<int MODE>
__global__ __launch_bounds__(256, 2) void gemm_mma(
    const __half* __restrict__ Ah, const __half* __restrict__ Al,
    const __half* __restrict__ Bw,
    float* __restrict__ outF, __half* __restrict__ o1,
    __half* __restrict__ o2, __half* __restrict__ o3)
{
    extern __shared__ __align__(16) char smem[];
    const int tid = threadIdx.x;
    const int wid = tid >> 5, lane = tid & 31;
    const int g = lane >> 2, tg = lane & 3;
    const int m0 = blockIdx.y * 128, n0 = blockIdx.x * 128;
    const int wm = (wid & 1) * 64, wn = (wid >> 1) * 32;
    const int z = (MODE == 1) ? blockIdx.z : 0;

    const uint32_t sbase = smem_u32(smem);
    const __half* Bz = (MODE == 1) ? (Bw + (size_t)z * DD * DD) : Bw;
    const __half* srcs[3] = {Ah, Al, Bz};

    auto prefetch = [&](int s) {
        const int k0 = s * KS;
        const uint32_t dst0 = sbase + (uint32_t)(s % 3) * STAGE_BYTES;
#pragma unroll
        for (int t = 0; t < 3; t++) {
            const __half* sp = srcs[t];
            const int rb = (t < 2) ? m0 : n0;
#pragma unroll
            for (int i = 0; i < 2; i++) {
                int idx = tid + i * 256;
                int row = idx >> 2, c = idx & 3;
                const void* gsrc = sp + (size_t)(rb + row) * DD + k0 + c * 8;
                CP_ASYNC16(dst0 + t * TILE_BYTES + row * RB + c * 16, gsrc);
            }
        }
        CP_COMMIT();
    };

    float acc[4][4][4];
#pragma unroll
    for (int i = 0; i < 4; i++)
#pragma unroll
        for (int j = 0; j < 4; j++)
#pragma unroll
            for (int c = 0; c < 4; c++) acc[i][j][c] = 0.f;

    const uint32_t laneA = (lane & 15) * RB + (lane >> 4) * 16;
    const uint32_t laneB = ((lane & 7) + (lane >> 4) * 8) * RB + ((lane >> 3) & 1) * 16;

    prefetch(0);
    prefetch(1);
    for (int s = 0; s < NSTG; s++) {
        if (s == NSTG - 1) { CP_WAIT0(); } else { CP_WAIT1(); }
        __syncthreads();
        if (s + 2 < NSTG) prefetch(s + 2);
        const uint32_t st = sbase + (uint32_t)(s % 3) * STAGE_BYTES;

#pragma unroll
        for (int ks = 0; ks < 2; ks++) {
            const int kb2 = ks * 32;
            uint32_t ah[4][4], al[4][4], bh[8];
#pragma unroll
            for (int i = 0; i < 4; i++) {
                uint32_t aA = st + (wm + 16 * i) * RB + kb2 + laneA;
                ldsm_x4(ah[i], aA);
                ldsm_x4(al[i], aA + TILE_BYTES);
            }
            {
                uint32_t b0 = st + 2 * TILE_BYTES + wn * RB + kb2 + laneB;
                ldsm_x4(bh,     b0);
                ldsm_x4(bh + 4, b0 + 16 * RB);
            }
#pragma unroll
            for (int i = 0; i < 4; i++)
#pragma unroll
                for (int j = 0; j < 4; j++) {
                    mma16816(acc[i][j], ah[i], bh + 2 * j);
                    mma16816(acc[i][j], al[i], bh + 2 * j);
                }
        }
    }

#pragma unroll
    for (int i = 0; i < 4; i++) {
        int mA = m0 + wm + i * 16 + g;
#pragma unroll
        for (int j = 0; j < 4; j++) {
            int c = n0 + wn + j * 8 + 2 * tg;
            if (MODE == 0) {
                *(float2*)(outF + (size_t)mA * DD + c) =
                    make_float2(acc[i][j][0], acc[i][j][1]);
                *(float2*)(outF + (size_t)(mA + 8) * DD + c) =
                    make_float2(acc[i][j][2], acc[i][j][3]);
            } else {
                int h = c >> 6, t = c & 63;
                int b1 = mA >> 10, n1 = mA & 1023;
                int b2 = (mA + 8) >> 10, n2 = (mA + 8) & 1023;
                size_t i1 = ((size_t)(b1 * HH + h) * NN + n1) * HD + t;
                size_t i2 = ((size_t)(b2 * HH + h) * NN + n2) * HD + t;
                if (z == 0) {
                    uint32_t hi, lo;
                    packsplit_h(acc[i][j][0] * 0.125f, acc[i][j][1] * 0.125f, hi, lo);
                    *(uint32_t*)(o1 + i1) = hi;
                    *(uint32_t*)(o2 + i1) = lo;
                    packsplit_h(acc[i][j][2] * 0.125f, acc[i][j][3] * 0.125f, hi, lo);
                    *(uint32_t*)(o1 + i2) = hi;
                    *(uint32_t*)(o2 + i2) = lo;
                } else {
                    __half* dst = (z == 1) ? o3 : (o3 + (size_t)BH * NN * HD);
                    *(uint32_t*)(dst + i1) = pack_h(acc[i][j][0], acc[i][j][1]);
                    *(uint32_t*)(dst + i2) = pack_h(acc[i][j][2], acc[i][j][3]);
                }
            }
        }
    }
}

// ---------------- flash attention (fp16 2-term, swizzled smem, 2 CTA/SM) ----------------
// R14-proven structure. Grid swapped to (qtile, bh) so consecutively-scheduled
// CTAs share the same bh => K/V tiles become L2-resident.
#define ATILE 16384                    // 128 rows x 128 B (swizzled)
#define AKV_STAGE (2*ATILE)            // 32768: K, V
#define ASMEM (2*ATILE + 2*AKV_STAGE)  // 98304
#define SOFF 8.0f

__global__ __launch_bounds__(256, 2) void attn_mma(const float* __restrict__ bias)
{
    extern __shared__ __align__(1024) char smem[];
    const int tid = threadIdx.x, wid = tid >> 5, lane = tid & 31;
    const int g = lane >> 2, tg = lane & 3;
    const int bh = blockIdx.y;             // swapped: y = (b,h)
    const int row0 = blockIdx.x * 128;     // swapped: x = q tile (fastest)
    const int wq = wid * 16;
    const uint32_t sb = smem_u32(smem);

    const __half* qhp = g_qh + (size_t)bh * NN * HD;
    const __half* qlp = g_ql + (size_t)bh * NN * HD;
    const __half* kp  = g_k  + (size_t)bh * NN * HD;
    const __half* vp  = g_v  + (size_t)bh * NN * HD;

    auto issue_kv = [&](int c) {
        const uint32_t stg = sb + 2 * ATILE + (uint32_t)(c & 1) * AKV_STAGE;
#pragma unroll
        for (int i = 0; i < 4; i++) {
            int idx = tid + i * 256;
            int row = idx >> 3, ch = idx & 7;
            size_t go = (size_t)(c * 128 + row) * HD + ch * 8;
            uint32_t so = SWZ((uint32_t)(row * 128 + ch * 16));
            CP_ASYNC16(stg + so,         kp + go);
            CP_ASYNC16(stg + ATILE + so, vp + go);
        }
    };

#pragma unroll
    for (int i = 0; i < 4; i++) {
        int idx = tid + i * 256;
        int row = idx >> 3, ch = idx & 7;
        size_t go = (size_t)(row0 + row) * HD + ch * 8;
        uint32_t so = SWZ((uint32_t)(row * 128 + ch * 16));
        CP_ASYNC16(sb + so,         qhp + go);
        CP_ASYNC16(sb + ATILE + so, qlp + go);
    }
    issue_kv(0);
    CP_COMMIT();

    float sA[16][4];
    float O[8][4];
#pragma unroll
    for (int j = 0; j < 8; j++)
#pragma unroll
        for (int c = 0; c < 4; c++) O[j][c] = 0.f;
    float ls[2] = {0.f, 0.f};
    uint32_t qfh[4][4], qfl[4][4];

    const float* biasP = bias + ((size_t)bh * NN + row0 + wq + g) * NN + 2 * tg;

    for (int c = 0; c < 8; c++) {
        // ---- bias LDGs first: fly during the cp.async wait ----
        const float* bp = biasP + c * 128;
#pragma unroll
        for (int j = 0; j < 16; j++) {
            float2 u = *(const float2*)(bp + 8 * j);
            float2 w = *(const float2*)(bp + 8 * NN + 8 * j);
            sA[j][0] = u.x; sA[j][1] = u.y; sA[j][2] = w.x; sA[j][3] = w.y;
        }

        CP_WAIT0();
        __syncthreads();
        if (c == 0) {
#pragma unroll
            for (int t = 0; t < 4; t++) {
                uint32_t qoff = (uint32_t)((wq + (lane & 15)) * 128 + t * 32 + (lane >> 4) * 16);
                uint32_t qa = sb + SWZ(qoff);
                ldsm_x4(qfh[t], qa);
                ldsm_x4(qfl[t], qa + ATILE);
            }
        }
        if (c + 1 < 8) { issue_kv(c + 1); CP_COMMIT(); }

        const uint32_t kh_b = sb + 2 * ATILE + (uint32_t)(c & 1) * AKV_STAGE;

        // ---- S = bias + Q K^T ----
#pragma unroll 4
        for (int j = 0; j < 16; j++) {
            uint32_t kf[8];
            uint32_t koff = (uint32_t)((j * 8 + (lane & 7)) * 128 + (lane >> 3) * 16);
            ldsm_x4(kf,     kh_b + SWZ(koff));
            ldsm_x4(kf + 4, kh_b + SWZ(koff + 64));
#pragma unroll
            for (int t = 0; t < 4; t++) {
                mma16816(sA[j], qfh[t], kf + 2 * t);
                mma16816(sA[j], qfl[t], kf + 2 * t);
            }
        }

        // ---- P = exp(S - SOFF); accumulate row sums ----
        {
            float p0 = 0.f, p1 = 0.f;
#pragma unroll
            for (int j = 0; j < 16; j++) {
                float e0 = __expf(sA[j][0] - SOFF);
                float e1 = __expf(sA[j][1] - SOFF);
                float e2 = __expf(sA[j][2] - SOFF);
                float e3 = __expf(sA[j][3] - SOFF);
                sA[j][0] = e0; sA[j][1] = e1; sA[j][2] = e2; sA[j][3] = e3;
                p0 += e0 + e1;
                p1 += e2 + e3;
            }
            ls[0] += p0;
            ls[1] += p1;
        }

        // ---- O += P V  (P split hi/lo, V single) ----
        const uint32_t vh_b = kh_b + ATILE;
#pragma unroll 2
        for (int t = 0; t < 8; t++) {
            uint32_t aph[4], apl[4];
            packsplit_h(sA[2 * t][0],     sA[2 * t][1],     aph[0], apl[0]);
            packsplit_h(sA[2 * t][2],     sA[2 * t][3],     aph[1], apl[1]);
            packsplit_h(sA[2 * t + 1][0], sA[2 * t + 1][1], aph[2], apl[2]);
            packsplit_h(sA[2 * t + 1][2], sA[2 * t + 1][3], aph[3], apl[3]);
#pragma unroll
            for (int jp = 0; jp < 8; jp += 2) {
                uint32_t vf[4];
                uint32_t voff = (uint32_t)((t * 16 + (lane & 7) + ((lane >> 3) & 1) * 8) * 128
                                           + jp * 16 + (lane >> 4) * 16);
                ldsm_x4_t(vf, vh_b + SWZ(voff));
                mma16816(O[jp],     aph, vf);
                mma16816(O[jp],     apl, vf);
                mma16816(O[jp + 1], aph, vf + 2);
                mma16816(O[jp + 1], apl, vf + 2);
            }
        }
    }

    // ---- finalize ----
    float inv[2];
#pragma unroll
    for (int h = 0; h < 2; h++) {
        float v = ls[h];
        v += __shfl_xor_sync(0xffffffffu, v, 1);
        v += __shfl_xor_sync(0xffffffffu, v, 2);
        inv[h] = 1.0f / v;
    }
    const int b = bh >> 4, hh = bh & 15;
    const size_t r1 = ((size_t)(b * NN + row0 + wq + g)) * DD + hh * HD + 2 * tg;
    const size_t r2 = r1 + (size_t)8 * DD;
#pragma unroll
    for (int jo = 0; jo < 8; jo++) {
        uint32_t hi, lo;
        packsplit_h(O[jo][0] * inv[0], O[jo][1] * inv[0], hi, lo);
        *(uint32_t*)(g_oh + r1 + 8 * jo) = hi;
        *(uint32_t*)(g_ol + r1 + 8 * jo) = lo;
        packsplit_h(O[jo][2] * inv[1], O[jo][3] * inv[1], hi, lo);
        *(uint32_t*)(g_oh + r2 + 8 * jo) = hi;
        *(uint32_t*)(g_ol + r2 + 8 * jo) = lo;
    }
}

// ---------------- launch ----------------
extern "C" void kernel_launch(void* const* d_in, const int* in_sizes, int n_in,
                              void* d_out, int out_size)
{
    const float* x    = (const float*)d_in[0];
    const float* bias = (const float*)d_in[1];
    float* out = (float*)d_out;

    __half *xh, *xl, *wq, *qh, *ql, *kk, *oh, *ol;
    cudaGetSymbolAddress((void**)&xh, g_xh);
    cudaGetSymbolAddress((void**)&xl, g_xl);
    cudaGetSymbolAddress((void**)&wq, g_w);
    cudaGetSymbolAddress((void**)&qh, g_qh);
    cudaGetSymbolAddress((void**)&ql, g_ql);
    cudaGetSymbolAddress((void**)&kk, g_k);
    cudaGetSymbolAddress((void**)&oh, g_oh);
    cudaGetSymbolAddress((void**)&ol, g_ol);

    cudaFuncSetAttribute(gemm_mma<0>, cudaFuncAttributeMaxDynamicSharedMemorySize, GSMEM_BYTES);
    cudaFuncSetAttribute(gemm_mma<1>, cudaFuncAttributeMaxDynamicSharedMemorySize, GSMEM_BYTES);
    cudaFuncSetAttribute(attn_mma, cudaFuncAttributeMaxDynamicSharedMemorySize, ASMEM);

    const int NX = BB*NN*DD;
    const int NW = DD*DD;

    split_x_kernel<<<NX/512, 256>>>(x, xh, xl, NX/2);
    round_w4_kernel<<<dim3(NW/512, 4), 256>>>((const float*)d_in[2], (const float*)d_in[3],
                                              (const float*)d_in[4], (const float*)d_in[5],
                                              wq, NW/2);

    dim3 gqkv(DD/128, (BB*NN)/128, 3);
    gemm_mma<1><<<gqkv, 256, GSMEM_BYTES>>>(xh, xl, wq, nullptr, qh, ql, kk);

    attn_mma<<<dim3(NN/128, BH), 256, ASMEM>>>(bias);   // grid swapped: x=qtile, y=bh

    gemm_mma<0><<<dim3(DD/128, (BB*NN)/128), 256, GSMEM_BYTES>>>(
        oh, ol, wq + 3*(size_t)NW, out, nullptr, nullptr, nullptr);
}